// round 7
// baseline (speedup 1.0000x reference)
#include <cuda_runtime.h>
#include <math.h>
#include <stdint.h>

// Problem constants
#define BB 4
#define TT 4096
#define DD 1024
#define NC 512           // number of time chunks
#define LL (TT / NC)     // 8 timesteps per chunk
#define ROW (3 * DD)     // 3072 floats per (b,t)

// Scratch: per-chunk affine summaries and per-chunk initial states (~24 MiB).
__device__ float g_A[NC * BB * DD];
__device__ float g_S[NC * BB * DD];
__device__ float g_H[NC * BB * DD];

// ---- fast transcendentals (MUFU.TANH) -------------------------------------
__device__ __forceinline__ float tanh_fast(float v) {
    float r;
    asm("tanh.approx.f32 %0, %1;" : "=f"(r) : "f"(v));
    return r;
}
// sigmoid(v) = 0.5*tanh(0.5v) + 0.5 ; 1-sigmoid(v) = 0.5 - 0.5*tanh(0.5v)

// ---- loads/stores ----------------------------------------------------------
__device__ __forceinline__ float4 ldg_cs(const float* p) {   // streaming, read-once
    float4 v;
    asm("ld.global.nc.cs.v4.f32 {%0,%1,%2,%3}, [%4];"
        : "=f"(v.x), "=f"(v.y), "=f"(v.z), "=f"(v.w) : "l"(p));
    return v;
}
__device__ __forceinline__ void stg_cs(float* p, float4 v) { // streaming store
    asm volatile("st.global.cs.v4.f32 [%0], {%1,%2,%3,%4};"
                 :: "l"(p), "f"(v.x), "f"(v.y), "f"(v.z), "f"(v.w));
}

// ---------------------------------------------------------------------------
// Pass 1: per-chunk summary. h_chunk_end = A * h_chunk_start + S.
// One block = (chunk c, batch b); 256 threads x float4 = all 1024 channels.
// ---------------------------------------------------------------------------
__global__ __launch_bounds__(256) void k_pass1(const float* __restrict__ x,
                                               const float* __restrict__ carry) {
    const int b = blockIdx.y;
    const int c = blockIdx.x;
    const int d = threadIdx.x * 4;

    const float* xb = x + (long)(b * TT + c * LL) * ROW + d;

    float A[4] = {1.f, 1.f, 1.f, 1.f};
    float S[4] = {0.f, 0.f, 0.f, 0.f};

#pragma unroll
    for (int t = 0; t < LL; t++) {
        float4 ip4 = ldg_cs(xb + (long)t * ROW);
        float4 ig4 = ldg_cs(xb + (long)t * ROW + DD);
        float ip[4] = {ip4.x, ip4.y, ip4.z, ip4.w};
        float ig[4] = {ig4.x, ig4.y, ig4.z, ig4.w};
#pragma unroll
        for (int j = 0; j < 4; j++) {
            float tg  = tanh_fast(0.5f * ig[j]);
            float igs = fmaf(0.5f, tg, 0.5f);        // sigmoid(ig)
            float f   = fmaf(-0.5f, tg, 0.5f);       // 1 - sigmoid(ig)
            float sv  = tanh_fast(ip[j]) * igs;
            if (c == 0 && t == 0)
                sv += carry[b * DD + d + j] * f;
            A[j] = f * A[j];
            S[j] = fmaf(f, S[j], sv);
        }
    }

    const int idx = (c * BB + b) * DD + d;
    *(float4*)(&g_A[idx]) = make_float4(A[0], A[1], A[2], A[3]);
    *(float4*)(&g_S[idx]) = make_float4(S[0], S[1], S[2], S[3]);
}

// ---------------------------------------------------------------------------
// Pass 2: sequential scan over NC chunk summaries per channel.
// Grid: BB*8 blocks x 32 threads; block handles 128 channels of one batch.
// g_A/g_S should largely be L2 hits (streaming x loads were evict-first).
// ---------------------------------------------------------------------------
__global__ __launch_bounds__(32) void k_pass2(float* __restrict__ out) {
    const int b   = blockIdx.x >> 3;
    const int seg = blockIdx.x & 7;
    const int d   = seg * 128 + threadIdx.x * 4;

    float h[4] = {0.f, 0.f, 0.f, 0.f};
#pragma unroll 8
    for (int c = 0; c < NC; c++) {
        const int idx = (c * BB + b) * DD + d;
        *(float4*)(&g_H[idx]) = make_float4(h[0], h[1], h[2], h[3]);
        float4 A = *(const float4*)(&g_A[idx]);
        float4 S = *(const float4*)(&g_S[idx]);
        h[0] = fmaf(A.x, h[0], S.x);
        h[1] = fmaf(A.y, h[1], S.y);
        h[2] = fmaf(A.z, h[2], S.z);
        h[3] = fmaf(A.w, h[3], S.w);
    }
    // h_last
    *(float4*)(out + b * DD + d) = make_float4(h[0], h[1], h[2], h[3]);
}

// ---------------------------------------------------------------------------
// Pass 3: replay each chunk from its initial h; write y = tanh(h) * og.
// ---------------------------------------------------------------------------
__global__ __launch_bounds__(256) void k_pass3(const float* __restrict__ x,
                                               const float* __restrict__ carry,
                                               float* __restrict__ out) {
    const int b = blockIdx.y;
    const int c = blockIdx.x;
    const int d = threadIdx.x * 4;

    const float* xb = x + (long)(b * TT + c * LL) * ROW + d;
    float* yb = out + (long)BB * DD /* skip h_last */
                    + (long)(b * TT + c * LL) * DD + d;

    const int idx = (c * BB + b) * DD + d;
    float4 h4 = *(const float4*)(&g_H[idx]);
    float h[4] = {h4.x, h4.y, h4.z, h4.w};

#pragma unroll
    for (int t = 0; t < LL; t++) {
        float4 ip4 = ldg_cs(xb + (long)t * ROW);
        float4 ig4 = ldg_cs(xb + (long)t * ROW + DD);
        float4 og4 = ldg_cs(xb + (long)t * ROW + 2 * DD);
        float ip[4] = {ip4.x, ip4.y, ip4.z, ip4.w};
        float ig[4] = {ig4.x, ig4.y, ig4.z, ig4.w};
        float og[4] = {og4.x, og4.y, og4.z, og4.w};
        float y[4];
#pragma unroll
        for (int j = 0; j < 4; j++) {
            float tg  = tanh_fast(0.5f * ig[j]);
            float igs = fmaf(0.5f, tg, 0.5f);
            float f   = fmaf(-0.5f, tg, 0.5f);
            float sv  = tanh_fast(ip[j]) * igs;
            if (c == 0 && t == 0)
                sv += carry[b * DD + d + j] * f;
            h[j] = fmaf(f, h[j], sv);
            float to  = tanh_fast(0.5f * og[j]);
            float ogs = fmaf(0.5f, to, 0.5f);
            y[j] = tanh_fast(h[j]) * ogs;
        }
        stg_cs(yb + (long)t * DD, make_float4(y[0], y[1], y[2], y[3]));
    }
}

extern "C" void kernel_launch(void* const* d_in, const int* in_sizes, int n_in,
                              void* d_out, int out_size) {
    const float* x     = (const float*)d_in[0];
    const float* carry = (const float*)d_in[1];
    float* out         = (float*)d_out;

    dim3 grid13(NC, BB);
    k_pass1<<<grid13, 256>>>(x, carry);
    k_pass2<<<BB * 8, 32>>>(out);
    k_pass3<<<grid13, 256>>>(x, carry, out);
}

// round 8
// speedup vs baseline: 2.1619x; 2.1619x over previous
#include <cuda_runtime.h>
#include <math.h>
#include <stdint.h>

// Problem constants
#define BB 4
#define TT 4096
#define DD 1024
#define NC 512           // number of time chunks
#define LL (TT / NC)     // 8 timesteps per chunk
#define ROW (3 * DD)     // 3072 floats per (b,t)

// Scratch: per-chunk affine summaries and per-chunk initial states.
__device__ float g_A[NC * BB * DD];
__device__ float g_S[NC * BB * DD];
__device__ float g_H[NC * BB * DD];

// ---- fast transcendentals (MUFU.TANH) -------------------------------------
__device__ __forceinline__ float tanh_fast(float v) {
    float r;
    asm("tanh.approx.f32 %0, %1;" : "=f"(r) : "f"(v));
    return r;
}
// sigmoid(v) = 0.5*tanh(0.5v) + 0.5 ; 1-sigmoid(v) = 0.5 - 0.5*tanh(0.5v)

// ---- loads/stores ----------------------------------------------------------
__device__ __forceinline__ float4 ldg_cs(const float* p) {   // streaming, read-once
    float4 v;
    asm("ld.global.nc.cs.v4.f32 {%0,%1,%2,%3}, [%4];"
        : "=f"(v.x), "=f"(v.y), "=f"(v.z), "=f"(v.w) : "l"(p));
    return v;
}
__device__ __forceinline__ void stg_cs(float* p, float4 v) { // streaming store
    asm volatile("st.global.cs.v4.f32 [%0], {%1,%2,%3,%4};"
                 :: "l"(p), "f"(v.x), "f"(v.y), "f"(v.z), "f"(v.w));
}

// ---------------------------------------------------------------------------
// Pass 1: per-chunk summary. h_chunk_end = A * h_chunk_start + S.
// ---------------------------------------------------------------------------
__global__ __launch_bounds__(256) void k_pass1(const float* __restrict__ x,
                                               const float* __restrict__ carry) {
    const int b = blockIdx.y;
    const int c = blockIdx.x;
    const int d = threadIdx.x * 4;

    const float* xb = x + (long)(b * TT + c * LL) * ROW + d;

    float A[4] = {1.f, 1.f, 1.f, 1.f};
    float S[4] = {0.f, 0.f, 0.f, 0.f};

#pragma unroll
    for (int t = 0; t < LL; t++) {
        float4 ip4 = ldg_cs(xb + (long)t * ROW);
        float4 ig4 = ldg_cs(xb + (long)t * ROW + DD);
        float ip[4] = {ip4.x, ip4.y, ip4.z, ip4.w};
        float ig[4] = {ig4.x, ig4.y, ig4.z, ig4.w};
#pragma unroll
        for (int j = 0; j < 4; j++) {
            float tg  = tanh_fast(0.5f * ig[j]);
            float igs = fmaf(0.5f, tg, 0.5f);        // sigmoid(ig)
            float f   = fmaf(-0.5f, tg, 0.5f);       // 1 - sigmoid(ig)
            float sv  = tanh_fast(ip[j]) * igs;
            if (c == 0 && t == 0)
                sv += carry[b * DD + d + j] * f;
            A[j] = f * A[j];
            S[j] = fmaf(f, S[j], sv);
        }
    }

    const int idx = (c * BB + b) * DD + d;
    *(float4*)(&g_A[idx]) = make_float4(A[0], A[1], A[2], A[3]);
    *(float4*)(&g_S[idx]) = make_float4(S[0], S[1], S[2], S[3]);
}

// ---------------------------------------------------------------------------
// Pass 2: sequential scan over NC chunk summaries per channel, with an
// explicit register software pipeline (prefetch depth PF) so the dependent
// h-chain never waits on memory. Grid: BB*8 blocks x 32 threads.
// ---------------------------------------------------------------------------
#define PF 16
__global__ __launch_bounds__(32) void k_pass2(float* __restrict__ out) {
    const int b   = blockIdx.x >> 3;
    const int seg = blockIdx.x & 7;
    const int d   = seg * 128 + threadIdx.x * 4;

    // per-chunk stride in float4 units
    const int stride4 = (BB * DD) / 4;
    const float4* __restrict__ pA = (const float4*)&g_A[b * DD + d];
    const float4* __restrict__ pS = (const float4*)&g_S[b * DD + d];
    float4* __restrict__ pH = (float4*)&g_H[b * DD + d];

    float4 bufA[PF], bufS[PF];
#pragma unroll
    for (int i = 0; i < PF; i++) {
        bufA[i] = pA[i * stride4];
        bufS[i] = pS[i * stride4];
    }

    float h0 = 0.f, h1 = 0.f, h2 = 0.f, h3 = 0.f;

#pragma unroll 1
    for (int c = 0; c < NC; c += PF) {
#pragma unroll
        for (int i = 0; i < PF; i++) {
            float4 A = bufA[i];
            float4 S = bufS[i];
            const int nc_ = c + PF + i;
            if (nc_ < NC) {                       // prefetch PF ahead
                bufA[i] = pA[nc_ * stride4];
                bufS[i] = pS[nc_ * stride4];
            }
            pH[(c + i) * stride4] = make_float4(h0, h1, h2, h3);
            h0 = fmaf(A.x, h0, S.x);
            h1 = fmaf(A.y, h1, S.y);
            h2 = fmaf(A.z, h2, S.z);
            h3 = fmaf(A.w, h3, S.w);
        }
    }
    // h_last
    *(float4*)(out + b * DD + d) = make_float4(h0, h1, h2, h3);
}

// ---------------------------------------------------------------------------
// Pass 3: replay each chunk from its initial h; write y = tanh(h) * og.
// ---------------------------------------------------------------------------
__global__ __launch_bounds__(256) void k_pass3(const float* __restrict__ x,
                                               const float* __restrict__ carry,
                                               float* __restrict__ out) {
    const int b = blockIdx.y;
    const int c = blockIdx.x;
    const int d = threadIdx.x * 4;

    const float* xb = x + (long)(b * TT + c * LL) * ROW + d;
    float* yb = out + (long)BB * DD /* skip h_last */
                    + (long)(b * TT + c * LL) * DD + d;

    const int idx = (c * BB + b) * DD + d;
    float4 h4 = *(const float4*)(&g_H[idx]);
    float h[4] = {h4.x, h4.y, h4.z, h4.w};

#pragma unroll
    for (int t = 0; t < LL; t++) {
        float4 ip4 = ldg_cs(xb + (long)t * ROW);
        float4 ig4 = ldg_cs(xb + (long)t * ROW + DD);
        float4 og4 = ldg_cs(xb + (long)t * ROW + 2 * DD);
        float ip[4] = {ip4.x, ip4.y, ip4.z, ip4.w};
        float ig[4] = {ig4.x, ig4.y, ig4.z, ig4.w};
        float og[4] = {og4.x, og4.y, og4.z, og4.w};
        float y[4];
#pragma unroll
        for (int j = 0; j < 4; j++) {
            float tg  = tanh_fast(0.5f * ig[j]);
            float igs = fmaf(0.5f, tg, 0.5f);
            float f   = fmaf(-0.5f, tg, 0.5f);
            float sv  = tanh_fast(ip[j]) * igs;
            if (c == 0 && t == 0)
                sv += carry[b * DD + d + j] * f;
            h[j] = fmaf(f, h[j], sv);
            float to  = tanh_fast(0.5f * og[j]);
            float ogs = fmaf(0.5f, to, 0.5f);
            y[j] = tanh_fast(h[j]) * ogs;
        }
        stg_cs(yb + (long)t * DD, make_float4(y[0], y[1], y[2], y[3]));
    }
}

extern "C" void kernel_launch(void* const* d_in, const int* in_sizes, int n_in,
                              void* d_out, int out_size) {
    const float* x     = (const float*)d_in[0];
    const float* carry = (const float*)d_in[1];
    float* out         = (float*)d_out;

    dim3 grid13(NC, BB);
    k_pass1<<<grid13, 256>>>(x, carry);
    k_pass2<<<BB * 8, 32>>>(out);
    k_pass3<<<grid13, 256>>>(x, carry, out);
}